// round 14
// baseline (speedup 1.0000x reference)
#include <cuda_runtime.h>
#include <cuda_bf16.h>
#include <math.h>
#include <cstdint>

// Problem constants
#define BATCH 64
#define TT    512
#define FF    1024
#define HH    1024
#define G4    4096
#define NCTA  256           // 64 N-groups x 4 K-splits, 2/SM co-resident
#define MROWS (BATCH * TT)

// ---------------- scratch (static device memory; no allocations) ------------
static __device__ float          g_xg[(size_t)MROWS * G4];
static __device__ __nv_bfloat16  g_xhi[(size_t)MROWS * FF];
static __device__ __nv_bfloat16  g_xlo[(size_t)MROWS * FF];
static __device__ __nv_bfloat16  g_wthi[(size_t)G4 * FF];     // WxT [n][k]
static __device__ __nv_bfloat16  g_wtlo[(size_t)G4 * FF];
static __device__ __nv_bfloat16  g_whthi[(size_t)G4 * HH];    // WhT [n][k]
static __device__ __nv_bfloat16  g_whtlo[(size_t)G4 * HH];
static __device__ __nv_bfloat16  g_hhi[2][BATCH * HH];
static __device__ __nv_bfloat16  g_hlo[2][BATCH * HH];
static __device__ float          g_zpart[NCTA * BATCH * 64];  // [g*4+ks][b][64]
static __device__ unsigned       g_flags[64];                 // per-group arrivals
static __device__ unsigned       g_bar_count;
static __device__ volatile unsigned g_bar_gen;

// ======================= PTX helpers ========================================
__device__ __forceinline__ uint32_t smem_u32(const void* p) {
    uint32_t a;
    asm("{ .reg .u64 t; cvta.to.shared.u64 t, %1; cvt.u32.u64 %0, t; }"
        : "=r"(a) : "l"(p));
    return a;
}
__device__ __forceinline__ void ldsm_x4(uint32_t& r0, uint32_t& r1,
                                        uint32_t& r2, uint32_t& r3, uint32_t addr) {
    asm volatile("ldmatrix.sync.aligned.m8n8.x4.shared.b16 {%0,%1,%2,%3}, [%4];"
                 : "=r"(r0), "=r"(r1), "=r"(r2), "=r"(r3) : "r"(addr));
}
__device__ __forceinline__ void mma16816(float* d, const uint32_t* a, const uint32_t* b) {
    asm volatile(
        "mma.sync.aligned.m16n8k16.row.col.f32.bf16.bf16.f32 "
        "{%0,%1,%2,%3}, {%4,%5,%6,%7}, {%8,%9}, {%0,%1,%2,%3};"
        : "+f"(d[0]), "+f"(d[1]), "+f"(d[2]), "+f"(d[3])
        : "r"(a[0]), "r"(a[1]), "r"(a[2]), "r"(a[3]), "r"(b[0]), "r"(b[1]));
}
__device__ __forceinline__ void cpasync16(uint32_t dst, const void* src) {
    asm volatile("cp.async.cg.shared.global [%0], [%1], 16;" :: "r"(dst), "l"(src));
}
__device__ __forceinline__ void cpcommit() { asm volatile("cp.async.commit_group;" ::: "memory"); }
template<int N> __device__ __forceinline__ void cpwait() {
    asm volatile("cp.async.wait_group %0;" :: "n"(N) : "memory");
}
// 64B-row swizzle (4 segs)
__device__ __forceinline__ uint32_t sw64(int row, int seg) {
    return (uint32_t)(row * 64 + ((seg ^ ((row >> 1) & 3)) << 4));
}
// 128B-row swizzle (8 segs)
__device__ __forceinline__ uint32_t swA3(int row, int seg) {
    return (uint32_t)((row << 7) + ((seg ^ (row & 7)) << 4));
}
// 512B-row swizzle (32 segs)
__device__ __forceinline__ uint32_t swB3(int n, int seg) {
    return (uint32_t)((n << 9) + ((seg ^ (n & 7)) << 4));
}

// ============================================================================
// Conversions
// ============================================================================
__global__ __launch_bounds__(256)
void convert_x_kernel(const float* __restrict__ x)
{
    size_t i = (size_t)blockIdx.x * blockDim.x + threadIdx.x;
    float4 v = ((const float4*)x)[i];
    float vv[4] = {v.x, v.y, v.z, v.w};
    __nv_bfloat16 hi[4], lo[4];
#pragma unroll
    for (int j = 0; j < 4; j++) {
        hi[j] = __float2bfloat16(vv[j]);
        lo[j] = __float2bfloat16(vv[j] - __bfloat162float(hi[j]));
    }
    __nv_bfloat162* xh = (__nv_bfloat162*)g_xhi;
    __nv_bfloat162* xl = (__nv_bfloat162*)g_xlo;
    xh[2 * i]     = __halves2bfloat162(hi[0], hi[1]);
    xh[2 * i + 1] = __halves2bfloat162(hi[2], hi[3]);
    xl[2 * i]     = __halves2bfloat162(lo[0], lo[1]);
    xl[2 * i + 1] = __halves2bfloat162(lo[2], lo[3]);
}

__global__ __launch_bounds__(256)
void convert_wt_kernel(const float* __restrict__ src, int which)
{
    __nv_bfloat16* dhi = which ? g_whthi : g_wthi;
    __nv_bfloat16* dlo = which ? g_whtlo : g_wtlo;
    size_t idx = (size_t)blockIdx.x * blockDim.x + threadIdx.x;
    int k = (int)(idx >> 12);
    int n = (int)(idx & 4095);
    float v = src[idx];
    __nv_bfloat16 hi = __float2bfloat16(v);
    __nv_bfloat16 lo = __float2bfloat16(v - __bfloat162float(hi));
    dhi[(size_t)n * FF + k] = hi;
    dlo[(size_t)n * FF + k] = lo;
}

// ============================================================================
// Fused persistent kernel: xg tiles (interleaved) + LSTM recurrence.
// SMEM: Bhi 32K | Blo 32K | work area 32K (GEMM A-chunks OR xg-tile stages).
// ============================================================================
#define P2_BHI   0
#define P2_BLO   32768
#define P2_A     65536
#define P2_ABUF  16384
#define P2_SMEM  (65536 + 32768 + 1024)

__device__ __forceinline__ float sigmoidf_(float v) { return 1.f / (1.f + expf(-v)); }

// One 64x64 xg tile: g_xg[row0..row0+63][col0..col0+63] = x @ Wx (bf16x3).
// Uses smem work area [P2_A, P2_A+32K): 2 stages of 16K
// (Ahi 4K | Alo 4K | Bhi 4K | Blo 4K per stage). KC=32, 32 chunks.
__device__ void do_xg_tile(char* smem, uint32_t sb, int tid, int row0, int col0)
{
    const int wid  = tid >> 5;
    const int lane = tid & 31;
    const int wm   = wid & 3;       // m16 block
    const int wn   = wid >> 2;      // n32 block (0..1)
    const int tr   = tid >> 2;      // staging row 0..63
    const int tsg  = tid & 3;       // staging seg 0..3

    float acc[4][4];
#pragma unroll
    for (int j = 0; j < 4; j++)
#pragma unroll
        for (int q = 0; q < 4; q++) acc[j][q] = 0.f;

    const uint32_t so_st = sw64(tr, tsg);

    auto issue = [&](int c) {
        const uint32_t stg = sb + P2_A + (uint32_t)(c & 1) * 16384;
        const int k0 = c * 32;
        const size_t sa = (size_t)(row0 + tr) * FF + k0 + tsg * 8;
        const size_t sbn = (size_t)(col0 + tr) * FF + k0 + tsg * 8;
        cpasync16(stg + 0     + so_st, g_xhi + sa);
        cpasync16(stg + 4096  + so_st, g_xlo + sa);
        cpasync16(stg + 8192  + so_st, g_wthi + sbn);
        cpasync16(stg + 12288 + so_st, g_wtlo + sbn);
        cpcommit();
    };

    issue(0);
    for (int c = 0; c < 32; c++) {
        if (c + 1 < 32) { issue(c + 1); cpwait<1>(); }
        else            { cpwait<0>(); }
        __syncthreads();

        const uint32_t stg = sb + P2_A + (uint32_t)(c & 1) * 16384;
#pragma unroll
        for (int kk = 0; kk < 2; kk++) {
            const int lrow = lane & 15;
            const int lseg = 2 * kk + (lane >> 4);

            uint32_t ah[4], al[4];
            ldsm_x4(ah[0], ah[1], ah[2], ah[3], stg + 0    + sw64(wm * 16 + lrow, lseg));
            ldsm_x4(al[0], al[1], al[2], al[3], stg + 4096 + sw64(wm * 16 + lrow, lseg));

            uint32_t bh[4][2], bl[4][2];
#pragma unroll
            for (int jj = 0; jj < 2; jj++) {
                const int r = wn * 32 + 16 * jj + lrow;
                uint32_t r0, r1, r2, r3;
                ldsm_x4(r0, r1, r2, r3, stg + 8192 + sw64(r, lseg));
                bh[2 * jj][0] = r0; bh[2 * jj][1] = r2;
                bh[2 * jj + 1][0] = r1; bh[2 * jj + 1][1] = r3;
                ldsm_x4(r0, r1, r2, r3, stg + 12288 + sw64(r, lseg));
                bl[2 * jj][0] = r0; bl[2 * jj][1] = r2;
                bl[2 * jj + 1][0] = r1; bl[2 * jj + 1][1] = r3;
            }
#pragma unroll
            for (int j = 0; j < 4; j++) {
                mma16816(acc[j], ah, bh[j]);
                mma16816(acc[j], ah, bl[j]);
                mma16816(acc[j], al, bh[j]);
            }
        }
        __syncthreads();
    }

    // epilogue
    const int tq = lane >> 2;
    const int trr = lane & 3;
    const int mbase = row0 + wm * 16;
#pragma unroll
    for (int j = 0; j < 4; j++) {
        const int nbase = col0 + wn * 32 + 8 * j;
        float* p0 = &g_xg[(size_t)(mbase + tq) * G4 + nbase + 2 * trr];
        float* p1 = &g_xg[(size_t)(mbase + tq + 8) * G4 + nbase + 2 * trr];
        p0[0] = acc[j][0]; p0[1] = acc[j][1];
        p1[0] = acc[j][2]; p1[1] = acc[j][3];
    }
}

__device__ __forceinline__ void grid_barrier(int tid)
{
    __threadfence();
    __syncthreads();
    if (tid == 0) {
        unsigned gen = g_bar_gen;
        if (atomicAdd(&g_bar_count, 1) == NCTA - 1) {
            g_bar_count = 0;
            __threadfence();
            g_bar_gen = gen + 1;
        } else {
            while (g_bar_gen == gen) { __nanosleep(32); }
        }
    }
    __syncthreads();
}

__global__ __launch_bounds__(256, 2)
void lstm_fused_kernel(const float* __restrict__ bias, float* __restrict__ out)
{
    extern __shared__ char smem_raw[];
    char* smem = (char*)(((uintptr_t)smem_raw + 1023) & ~(uintptr_t)1023);
    const uint32_t sb = smem_u32(smem);

    const int tid  = threadIdx.x;
    const int wid  = tid >> 5;
    const int lane = tid & 31;
    const int wm   = wid & 3;
    const int wn   = wid >> 2;
    const int blk  = blockIdx.x;
    const int g    = blk >> 2;
    const int ks   = blk & 3;
    const int kbase = ks * 256;

    __shared__ unsigned s_base;

    const int pb = ks * 16 + (tid >> 4);
    const int hl = tid & 15;
    const int hcol = g * 16 + hl;
    float bb[4];
#pragma unroll
    for (int gt = 0; gt < 4; gt++) bb[gt] = bias[gt * 1024 + hcol];
    float cell = 0.f;

    // ---- resident B (WhT slice): 64 n x 256 k, hi/lo ----
#pragma unroll
    for (int i = 0; i < 8; i++) {
        int fi  = tid + i * 256;
        int n   = fi >> 5;
        int seg = fi & 31;
        int gn  = (n >> 4) * 1024 + g * 16 + (n & 15);
        uint32_t so = swB3(n, seg);
        const size_t src = (size_t)gn * HH + kbase + seg * 8;
        *(float4*)(smem + P2_BHI + so) = *(const float4*)(g_whthi + src);
        *(float4*)(smem + P2_BLO + so) = *(const float4*)(g_whtlo + src);
    }
    __syncthreads();

    // ---- prologue: xg chunk 0 (t in [0,128)), 32 tiles per CTA ----
    for (int ti = 0; ti < 32; ti++) {
        const int tileIdx = blk * 32 + ti;
        const int mblk = tileIdx >> 6;      // 0..127
        const int nblk = tileIdx & 63;
        const int row0 = (mblk >> 1) * 512 + (mblk & 1) * 64;   // c=0
        do_xg_tile(smem, sb, tid, row0, nblk * 64);
    }
    grid_barrier(tid);

    const int ar  = tid >> 3;   // 0..31
    const int asg = tid & 7;
    float* zpart_self = g_zpart + (size_t)(g * 4 + ks) * BATCH * 64;

    for (int t = 0; t < TT; t++) {
        if (t == 0 && tid == 0) s_base = g_flags[g];
        __syncthreads();

        float xv[4];
#pragma unroll
        for (int gt = 0; gt < 4; gt++)
            xv[gt] = g_xg[((size_t)pb * TT + t) * G4 + gt * 1024 + hcol];

        if (t > 0) {
            const __nv_bfloat16* hh = g_hhi[(t - 1) & 1];
            const __nv_bfloat16* hl_ = g_hlo[(t - 1) & 1];

            float acc[4][4];
#pragma unroll
            for (int j = 0; j < 4; j++)
#pragma unroll
                for (int q = 0; q < 4; q++) acc[j][q] = 0.f;

            auto issueA = [&](int kc) {
                const uint32_t abase = P2_A + (uint32_t)(kc & 1) * P2_ABUF;
                const int kn = kbase + kc * 64;
#pragma unroll
                for (int i = 0; i < 2; i++) {
                    const int row = ar + 32 * i;
                    const uint32_t so = swA3(row, asg);
                    const size_t off = (size_t)row * HH + kn + asg * 8;
                    cpasync16(sb + abase + so,        hh  + off);
                    cpasync16(sb + abase + 8192 + so, hl_ + off);
                }
                cpcommit();
            };

            issueA(0);
            for (int kc = 0; kc < 4; kc++) {
                if (kc + 1 < 4) { issueA(kc + 1); cpwait<1>(); }
                else            { cpwait<0>(); }
                __syncthreads();

                const uint32_t abase = P2_A + (uint32_t)(kc & 1) * P2_ABUF;
#pragma unroll
                for (int kk = 0; kk < 4; kk++) {
                    const int lrow = lane & 15;
                    const int hs   = lane >> 4;
                    const int aseg2 = 2 * kk + hs;
                    const int bseg2 = 2 * (kc * 4 + kk) + hs;

                    uint32_t ah[4], al[4];
                    ldsm_x4(ah[0], ah[1], ah[2], ah[3],
                            sb + abase + swA3(wm * 16 + lrow, aseg2));
                    ldsm_x4(al[0], al[1], al[2], al[3],
                            sb + abase + 8192 + swA3(wm * 16 + lrow, aseg2));

                    uint32_t bh[4][2], bl[4][2];
#pragma unroll
                    for (int jj = 0; jj < 2; jj++) {
                        const int r = wn * 32 + 16 * jj + lrow;
                        uint32_t r0, r1, r2, r3;
                        ldsm_x4(r0, r1, r2, r3, sb + P2_BHI + swB3(r, bseg2));
                        bh[2 * jj][0] = r0; bh[2 * jj][1] = r2;
                        bh[2 * jj + 1][0] = r1; bh[2 * jj + 1][1] = r3;
                        ldsm_x4(r0, r1, r2, r3, sb + P2_BLO + swB3(r, bseg2));
                        bl[2 * jj][0] = r0; bl[2 * jj][1] = r2;
                        bl[2 * jj + 1][0] = r1; bl[2 * jj + 1][1] = r3;
                    }
#pragma unroll
                    for (int j = 0; j < 4; j++) {
                        mma16816(acc[j], ah, bh[j]);
                        mma16816(acc[j], ah, bl[j]);
                        mma16816(acc[j], al, bh[j]);
                    }
                }
                __syncthreads();
            }

            // write partials
            {
                const int r = wm * 16 + (lane >> 2);
#pragma unroll
                for (int j = 0; j < 4; j++) {
                    const int n = wn * 32 + 8 * j + (lane & 3) * 2;
                    zpart_self[r * 64 + n]           = acc[j][0];
                    zpart_self[r * 64 + n + 1]       = acc[j][1];
                    zpart_self[(r + 8) * 64 + n]     = acc[j][2];
                    zpart_self[(r + 8) * 64 + n + 1] = acc[j][3];
                }
            }

            // per-group flag sync (release only; consumers use __ldcv)
            __threadfence();
            __syncthreads();
            if (tid == 0) {
                atomicAdd(&g_flags[g], 1u);
                const unsigned tgt = s_base + 4u * (unsigned)t;
                while ((int)(*(volatile unsigned*)&g_flags[g] - tgt) < 0)
                    __nanosleep(32);
            }
            __syncthreads();
        }

        // ---- pointwise (zpart via __ldcv) ----
        {
            float z[4];
#pragma unroll
            for (int gt = 0; gt < 4; gt++) {
                float s = xv[gt] + bb[gt];
                if (t > 0) {
                    const int n = gt * 16 + hl;
#pragma unroll
                    for (int k2 = 0; k2 < 4; k2++)
                        s += __ldcv(&g_zpart[((size_t)(g * 4 + k2) * BATCH + pb) * 64 + n]);
                }
                z[gt] = s;
            }
            float cn = sigmoidf_(z[1]) * cell + sigmoidf_(z[0]) * tanhf(z[2]);
            float hn = sigmoidf_(z[3]) * tanhf(cn);
            cell = cn;

            out[((size_t)pb * TT + t) * HH + hcol] = hn;
            __nv_bfloat16 hi = __float2bfloat16(hn);
            __nv_bfloat16 lo = __float2bfloat16(hn - __bfloat162float(hi));
            g_hhi[t & 1][pb * HH + hcol] = hi;
            g_hlo[t & 1][pb * HH + hcol] = lo;
        }

        // ---- inject one future xg tile every 4th step (chunks 1..3) ----
        if (t < 384 && (t & 3) == 0) {
            const int c = (t >> 7) + 1;         // 1..3
            const int ti = (t & 127) >> 2;      // 0..31
            const int tileIdx = blk * 32 + ti;
            const int mblk = tileIdx >> 6;
            const int nblk = tileIdx & 63;
            const int row0 = (mblk >> 1) * 512 + c * 128 + (mblk & 1) * 64;
            do_xg_tile(smem, sb, tid, row0, nblk * 64);
        }

        // ---- grid parity barrier (h + injected-xg visibility) ----
        grid_barrier(tid);
    }
}

// ============================================================================
// Launch: 4 graph nodes.
// ============================================================================
extern "C" void kernel_launch(void* const* d_in, const int* in_sizes, int n_in,
                              void* d_out, int out_size)
{
    const float* x  = (const float*)d_in[0];
    const float* Wx = (const float*)d_in[1];
    const float* Wh = (const float*)d_in[2];
    const float* b  = (const float*)d_in[3];
    float* out = (float*)d_out;

    cudaFuncSetAttribute(lstm_fused_kernel,
                         cudaFuncAttributeMaxDynamicSharedMemorySize, P2_SMEM);

    convert_x_kernel<<<(int)(((size_t)MROWS * FF / 4) / 256), 256>>>(x);
    convert_wt_kernel<<<(int)(((size_t)FF * G4) / 256), 256>>>(Wx, 0);
    convert_wt_kernel<<<(int)(((size_t)FF * G4) / 256), 256>>>(Wh, 1);

    lstm_fused_kernel<<<NCTA, 256, P2_SMEM>>>(b, out);
}

// round 15
// speedup vs baseline: 1.1128x; 1.1128x over previous
#include <cuda_runtime.h>
#include <cuda_bf16.h>
#include <math.h>
#include <cstdint>

// Problem constants
#define BATCH 64
#define TT    512
#define FF    1024
#define HH    1024
#define G4    4096
#define NCTA  256           // 64 N-groups x 4 K-splits, 2/SM co-resident
#define MROWS (BATCH * TT)

// ---------------- scratch (static device memory; no allocations) ------------
static __device__ float          g_xg[(size_t)MROWS * G4];
static __device__ __nv_bfloat16  g_xhi[(size_t)MROWS * FF];
static __device__ __nv_bfloat16  g_xlo[(size_t)MROWS * FF];
static __device__ __nv_bfloat16  g_wthi[(size_t)G4 * FF];     // WxT [n][k]
static __device__ __nv_bfloat16  g_wtlo[(size_t)G4 * FF];
static __device__ __nv_bfloat16  g_whthi[(size_t)G4 * HH];    // WhT [n][k]
static __device__ __nv_bfloat16  g_whtlo[(size_t)G4 * HH];
static __device__ __nv_bfloat16  g_hhi[2][BATCH * HH];
static __device__ __nv_bfloat16  g_hlo[2][BATCH * HH];
static __device__ float          g_zpart[NCTA * BATCH * 64];  // [g*4+ks][b][64]
static __device__ unsigned       g_flags[64];                 // zpart arrivals / group
static __device__ unsigned       g_flags2[64];                // pointwise arrivals / group
static __device__ unsigned       g_bar_count;
static __device__ volatile unsigned g_bar_gen;

// ======================= PTX helpers ========================================
__device__ __forceinline__ uint32_t smem_u32(const void* p) {
    uint32_t a;
    asm("{ .reg .u64 t; cvta.to.shared.u64 t, %1; cvt.u32.u64 %0, t; }"
        : "=r"(a) : "l"(p));
    return a;
}
__device__ __forceinline__ void ldsm_x4(uint32_t& r0, uint32_t& r1,
                                        uint32_t& r2, uint32_t& r3, uint32_t addr) {
    asm volatile("ldmatrix.sync.aligned.m8n8.x4.shared.b16 {%0,%1,%2,%3}, [%4];"
                 : "=r"(r0), "=r"(r1), "=r"(r2), "=r"(r3) : "r"(addr));
}
__device__ __forceinline__ void mma16816(float* d, const uint32_t* a, const uint32_t* b) {
    asm volatile(
        "mma.sync.aligned.m16n8k16.row.col.f32.bf16.bf16.f32 "
        "{%0,%1,%2,%3}, {%4,%5,%6,%7}, {%8,%9}, {%0,%1,%2,%3};"
        : "+f"(d[0]), "+f"(d[1]), "+f"(d[2]), "+f"(d[3])
        : "r"(a[0]), "r"(a[1]), "r"(a[2]), "r"(a[3]), "r"(b[0]), "r"(b[1]));
}
__device__ __forceinline__ void cpasync16(uint32_t dst, const void* src) {
    asm volatile("cp.async.cg.shared.global [%0], [%1], 16;" :: "r"(dst), "l"(src));
}
__device__ __forceinline__ void cpcommit() { asm volatile("cp.async.commit_group;" ::: "memory"); }
template<int N> __device__ __forceinline__ void cpwait() {
    asm volatile("cp.async.wait_group %0;" :: "n"(N) : "memory");
}
__device__ __forceinline__ uint32_t swA3(int row, int seg) {
    return (uint32_t)((row << 7) + ((seg ^ (row & 7)) << 4));
}
__device__ __forceinline__ uint32_t swB3(int n, int seg) {
    return (uint32_t)((n << 9) + ((seg ^ (n & 7)) << 4));
}

// ============================================================================
// Conversions
// ============================================================================
__global__ __launch_bounds__(256)
void convert_x_kernel(const float* __restrict__ x)
{
    size_t i = (size_t)blockIdx.x * blockDim.x + threadIdx.x;
    float4 v = ((const float4*)x)[i];
    float vv[4] = {v.x, v.y, v.z, v.w};
    __nv_bfloat16 hi[4], lo[4];
#pragma unroll
    for (int j = 0; j < 4; j++) {
        hi[j] = __float2bfloat16(vv[j]);
        lo[j] = __float2bfloat16(vv[j] - __bfloat162float(hi[j]));
    }
    __nv_bfloat162* xh = (__nv_bfloat162*)g_xhi;
    __nv_bfloat162* xl = (__nv_bfloat162*)g_xlo;
    xh[2 * i]     = __halves2bfloat162(hi[0], hi[1]);
    xh[2 * i + 1] = __halves2bfloat162(hi[2], hi[3]);
    xl[2 * i]     = __halves2bfloat162(lo[0], lo[1]);
    xl[2 * i + 1] = __halves2bfloat162(lo[2], lo[3]);
}

__global__ __launch_bounds__(256)
void convert_wt_kernel(const float* __restrict__ src, int which)
{
    __nv_bfloat16* dhi = which ? g_whthi : g_wthi;
    __nv_bfloat16* dlo = which ? g_whtlo : g_wtlo;
    size_t idx = (size_t)blockIdx.x * blockDim.x + threadIdx.x;
    int k = (int)(idx >> 12);
    int n = (int)(idx & 4095);
    float v = src[idx];
    __nv_bfloat16 hi = __float2bfloat16(v);
    __nv_bfloat16 lo = __float2bfloat16(v - __bfloat162float(hi));
    dhi[(size_t)n * FF + k] = hi;
    dlo[(size_t)n * FF + k] = lo;
}

// ============================================================================
// Phase 1: xg = x @ Wx. CTA 128x64, warp m32n32, KCHUNK=64, cp.async 2-stage.
// (validated R13)
// ============================================================================
#define P1_AHI 0
#define P1_ALO 16384
#define P1_BHI 32768
#define P1_BLO 40960
#define P1_BUF 49152
#define SMEM_DYN (2 * P1_BUF + 1024)
#define NCH1 16

__global__ __launch_bounds__(256, 2)
void gemm_mma_kernel()
{
    extern __shared__ char smem_raw[];
    char* smem = (char*)(((uintptr_t)smem_raw + 1023) & ~(uintptr_t)1023);
    const uint32_t sb = smem_u32(smem);

    const int tid = threadIdx.x;
    const int wid = tid >> 5;
    const int lane = tid & 31;
    const int wm = wid & 3;
    const int wn = wid >> 2;
    const int col0 = blockIdx.x * 64;
    const int row0 = blockIdx.y * 128;

    const int sr  = tid >> 3;
    const int ssg = tid & 7;

    float acc[2][4][4];
#pragma unroll
    for (int i = 0; i < 2; i++)
#pragma unroll
        for (int j = 0; j < 4; j++)
#pragma unroll
            for (int q = 0; q < 4; q++) acc[i][j][q] = 0.f;

    auto issue = [&](int c) {
        const uint32_t stg = (uint32_t)(c & 1) * P1_BUF;
        const int k0 = c * 64;
#pragma unroll
        for (int i = 0; i < 4; i++) {
            const int row = sr + 32 * i;
            const uint32_t so = swA3(row, ssg);
            const size_t src = (size_t)(row0 + row) * FF + k0 + ssg * 8;
            cpasync16(sb + stg + P1_AHI + so, g_xhi + src);
            cpasync16(sb + stg + P1_ALO + so, g_xlo + src);
        }
#pragma unroll
        for (int i = 0; i < 2; i++) {
            const int n = sr + 32 * i;
            const uint32_t so = swA3(n, ssg);
            const size_t src = (size_t)(col0 + n) * FF + k0 + ssg * 8;
            cpasync16(sb + stg + P1_BHI + so, g_wthi + src);
            cpasync16(sb + stg + P1_BLO + so, g_wtlo + src);
        }
        cpcommit();
    };

    issue(0);
    for (int c = 0; c < NCH1; c++) {
        if (c + 1 < NCH1) { issue(c + 1); cpwait<1>(); }
        else             { cpwait<0>(); }
        __syncthreads();

        const uint32_t stg = (uint32_t)(c & 1) * P1_BUF;
#pragma unroll
        for (int kk = 0; kk < 4; kk++) {
            const int lrow = lane & 15;
            const int lseg = 2 * kk + (lane >> 4);

            uint32_t ah[2][4], al[2][4];
#pragma unroll
            for (int i = 0; i < 2; i++) {
                const int r = 32 * wm + 16 * i + lrow;
                ldsm_x4(ah[i][0], ah[i][1], ah[i][2], ah[i][3],
                        sb + stg + P1_AHI + swA3(r, lseg));
                ldsm_x4(al[i][0], al[i][1], al[i][2], al[i][3],
                        sb + stg + P1_ALO + swA3(r, lseg));
            }
            uint32_t bh[4][2], bl[4][2];
#pragma unroll
            for (int jj = 0; jj < 2; jj++) {
                const int r = 32 * wn + 16 * jj + lrow;
                uint32_t r0, r1, r2, r3;
                ldsm_x4(r0, r1, r2, r3, sb + stg + P1_BHI + swA3(r, lseg));
                bh[2 * jj][0] = r0; bh[2 * jj][1] = r2;
                bh[2 * jj + 1][0] = r1; bh[2 * jj + 1][1] = r3;
                ldsm_x4(r0, r1, r2, r3, sb + stg + P1_BLO + swA3(r, lseg));
                bl[2 * jj][0] = r0; bl[2 * jj][1] = r2;
                bl[2 * jj + 1][0] = r1; bl[2 * jj + 1][1] = r3;
            }
#pragma unroll
            for (int i = 0; i < 2; i++)
#pragma unroll
                for (int j = 0; j < 4; j++) {
                    mma16816(acc[i][j], ah[i], bh[j]);
                    mma16816(acc[i][j], ah[i], bl[j]);
                    mma16816(acc[i][j], al[i], bh[j]);
                }
        }
        __syncthreads();
    }

    const int tq = lane >> 2;
    const int tr = lane & 3;
#pragma unroll
    for (int i = 0; i < 2; i++) {
        const int mbase = row0 + 32 * wm + 16 * i;
#pragma unroll
        for (int j = 0; j < 4; j++) {
            const int nbase = col0 + 32 * wn + 8 * j;
            float* p0 = &g_xg[(size_t)(mbase + tq) * G4 + nbase + 2 * tr];
            float* p1 = &g_xg[(size_t)(mbase + tq + 8) * G4 + nbase + 2 * tr];
            p0[0] = acc[i][j][0]; p0[1] = acc[i][j][1];
            p1[0] = acc[i][j][2]; p1[1] = acc[i][j][3];
        }
    }
}

// ============================================================================
// Phase 2: persistent K-split recurrence (R13 core) + two-level tree barrier.
// ============================================================================
#define P2_BHI   0
#define P2_BLO   32768
#define P2_A     65536
#define P2_ABUF  16384
#define P2_SMEM  (65536 + 32768 + 1024)

__device__ __forceinline__ float sigmoidf_(float v) { return 1.f / (1.f + expf(-v)); }

__global__ __launch_bounds__(256, 2)
void lstm_mma_kernel(const float* __restrict__ bias, float* __restrict__ out)
{
    extern __shared__ char smem_raw[];
    char* smem = (char*)(((uintptr_t)smem_raw + 1023) & ~(uintptr_t)1023);
    const uint32_t sb = smem_u32(smem);

    const int tid  = threadIdx.x;
    const int wid  = tid >> 5;
    const int lane = tid & 31;
    const int wm   = wid & 3;
    const int wn   = wid >> 2;
    const int g    = blockIdx.x >> 2;
    const int ks   = blockIdx.x & 3;
    const int kbase = ks * 256;

    __shared__ unsigned s_base, s_base2;

    const int pb = ks * 16 + (tid >> 4);
    const int hl = tid & 15;
    const int hcol = g * 16 + hl;
    float bb[4];
#pragma unroll
    for (int gt = 0; gt < 4; gt++) bb[gt] = bias[gt * 1024 + hcol];
    float cell = 0.f;

    // ---- resident B: 64 n x 256 k slice, hi/lo ----
#pragma unroll
    for (int i = 0; i < 8; i++) {
        int fi  = tid + i * 256;
        int n   = fi >> 5;
        int seg = fi & 31;
        int gn  = (n >> 4) * 1024 + g * 16 + (n & 15);
        uint32_t so = swB3(n, seg);
        const size_t src = (size_t)gn * HH + kbase + seg * 8;
        *(float4*)(smem + P2_BHI + so) = *(const float4*)(g_whthi + src);
        *(float4*)(smem + P2_BLO + so) = *(const float4*)(g_whtlo + src);
    }

    // ---- capture flag bases; full 256-arrival prologue barrier ----
    unsigned gen_seen = 0;
    if (tid == 0) { s_base = g_flags[g]; s_base2 = g_flags2[g]; }
    __threadfence();
    __syncthreads();
    if (tid == 0) {
        unsigned gen = g_bar_gen;
        if (atomicAdd(&g_bar_count, 1) == NCTA - 1) {
            g_bar_count = 0;
            __threadfence();
            g_bar_gen = gen + 1;
        } else {
            while (g_bar_gen == gen) { __nanosleep(32); }
        }
        gen_seen = g_bar_gen;     // generation after prologue release
    }
    __syncthreads();

    const int ar  = tid >> 3;
    const int asg = tid & 7;
    float* zpart_self = g_zpart + (size_t)(g * 4 + ks) * BATCH * 64;

    for (int t = 0; t < TT; t++) {
        float xv[4];
#pragma unroll
        for (int gt = 0; gt < 4; gt++)
            xv[gt] = g_xg[((size_t)pb * TT + t) * G4 + gt * 1024 + hcol];

        if (t > 0) {
            const __nv_bfloat16* hh = g_hhi[(t - 1) & 1];
            const __nv_bfloat16* hl_ = g_hlo[(t - 1) & 1];

            float acc[4][4];
#pragma unroll
            for (int j = 0; j < 4; j++)
#pragma unroll
                for (int q = 0; q < 4; q++) acc[j][q] = 0.f;

            auto issueA = [&](int kc) {
                const uint32_t abase = P2_A + (uint32_t)(kc & 1) * P2_ABUF;
                const int kn = kbase + kc * 64;
#pragma unroll
                for (int i = 0; i < 2; i++) {
                    const int row = ar + 32 * i;
                    const uint32_t so = swA3(row, asg);
                    const size_t off = (size_t)row * HH + kn + asg * 8;
                    cpasync16(sb + abase + so,        hh  + off);
                    cpasync16(sb + abase + 8192 + so, hl_ + off);
                }
                cpcommit();
            };

            issueA(0);
            for (int kc = 0; kc < 4; kc++) {
                if (kc + 1 < 4) { issueA(kc + 1); cpwait<1>(); }
                else            { cpwait<0>(); }
                __syncthreads();

                const uint32_t abase = P2_A + (uint32_t)(kc & 1) * P2_ABUF;
#pragma unroll
                for (int kk = 0; kk < 4; kk++) {
                    const int lrow = lane & 15;
                    const int hs   = lane >> 4;
                    const int aseg2 = 2 * kk + hs;
                    const int bseg2 = 2 * (kc * 4 + kk) + hs;

                    uint32_t ah[4], al[4];
                    ldsm_x4(ah[0], ah[1], ah[2], ah[3],
                            sb + abase + swA3(wm * 16 + lrow, aseg2));
                    ldsm_x4(al[0], al[1], al[2], al[3],
                            sb + abase + 8192 + swA3(wm * 16 + lrow, aseg2));

                    uint32_t bh[4][2], bl[4][2];
#pragma unroll
                    for (int jj = 0; jj < 2; jj++) {
                        const int r = wn * 32 + 16 * jj + lrow;
                        uint32_t r0, r1, r2, r3;
                        ldsm_x4(r0, r1, r2, r3, sb + P2_BHI + swB3(r, bseg2));
                        bh[2 * jj][0] = r0; bh[2 * jj][1] = r2;
                        bh[2 * jj + 1][0] = r1; bh[2 * jj + 1][1] = r3;
                        ldsm_x4(r0, r1, r2, r3, sb + P2_BLO + swB3(r, bseg2));
                        bl[2 * jj][0] = r0; bl[2 * jj][1] = r2;
                        bl[2 * jj + 1][0] = r1; bl[2 * jj + 1][1] = r3;
                    }
#pragma unroll
                    for (int j = 0; j < 4; j++) {
                        mma16816(acc[j], ah, bh[j]);
                        mma16816(acc[j], ah, bl[j]);
                        mma16816(acc[j], al, bh[j]);
                    }
                }
                __syncthreads();
            }

            // write partials
            {
                const int r = wm * 16 + (lane >> 2);
#pragma unroll
                for (int j = 0; j < 4; j++) {
                    const int n = wn * 32 + 8 * j + (lane & 3) * 2;
                    zpart_self[r * 64 + n]           = acc[j][0];
                    zpart_self[r * 64 + n + 1]       = acc[j][1];
                    zpart_self[(r + 8) * 64 + n]     = acc[j][2];
                    zpart_self[(r + 8) * 64 + n + 1] = acc[j][3];
                }
            }

            // per-group zpart flag sync (release; consumers use __ldcv)
            __threadfence();
            __syncthreads();
            if (tid == 0) {
                atomicAdd(&g_flags[g], 1u);
                const unsigned tgt = s_base + 4u * (unsigned)t;
                while ((int)(*(volatile unsigned*)&g_flags[g] - tgt) < 0)
                    __nanosleep(32);
            }
            __syncthreads();
        }

        // ---- pointwise (zpart via __ldcv) ----
        {
            float z[4];
#pragma unroll
            for (int gt = 0; gt < 4; gt++) {
                float s = xv[gt] + bb[gt];
                if (t > 0) {
                    const int n = gt * 16 + hl;
#pragma unroll
                    for (int k2 = 0; k2 < 4; k2++)
                        s += __ldcv(&g_zpart[((size_t)(g * 4 + k2) * BATCH + pb) * 64 + n]);
                }
                z[gt] = s;
            }
            float cn = sigmoidf_(z[1]) * cell + sigmoidf_(z[0]) * tanhf(z[2]);
            float hn = sigmoidf_(z[3]) * tanhf(cn);
            cell = cn;

            out[((size_t)pb * TT + t) * HH + hcol] = hn;
            __nv_bfloat16 hi = __float2bfloat16(hn);
            __nv_bfloat16 lo = __float2bfloat16(hn - __bfloat162float(hi));
            g_hhi[t & 1][pb * HH + hcol] = hi;
            g_hlo[t & 1][pb * HH + hcol] = lo;
        }

        // ---- two-level tree barrier: 64 global arrivals instead of 256 ----
        __threadfence();
        __syncthreads();
        if (tid == 0) {
            atomicAdd(&g_flags2[g], 1u);              // level 1 (64 addresses)
            if (ks == 0) {
                const unsigned tgt2 = s_base2 + 4u * (unsigned)(t + 1);
                while ((int)(*(volatile unsigned*)&g_flags2[g] - tgt2) < 0)
                    __nanosleep(32);
                if (atomicAdd(&g_bar_count, 1) == 63) {   // level 2 (64 arrivals)
                    g_bar_count = 0;
                    __threadfence();
                    g_bar_gen = gen_seen + 1;
                }
            }
            // all CTAs: wait for this step's global release
            const unsigned want = gen_seen + 1;
            while ((int)(g_bar_gen - want) < 0) { __nanosleep(32); }
            gen_seen = want;
        }
        __syncthreads();
    }
}

// ============================================================================
// Launch: 5 graph nodes.
// ============================================================================
extern "C" void kernel_launch(void* const* d_in, const int* in_sizes, int n_in,
                              void* d_out, int out_size)
{
    const float* x  = (const float*)d_in[0];
    const float* Wx = (const float*)d_in[1];
    const float* Wh = (const float*)d_in[2];
    const float* b  = (const float*)d_in[3];
    float* out = (float*)d_out;

    cudaFuncSetAttribute(gemm_mma_kernel,
                         cudaFuncAttributeMaxDynamicSharedMemorySize, SMEM_DYN);
    cudaFuncSetAttribute(lstm_mma_kernel,
                         cudaFuncAttributeMaxDynamicSharedMemorySize, P2_SMEM);

    convert_x_kernel<<<(int)(((size_t)MROWS * FF / 4) / 256), 256>>>(x);
    convert_wt_kernel<<<(int)(((size_t)FF * G4) / 256), 256>>>(Wx, 0);
    convert_wt_kernel<<<(int)(((size_t)FF * G4) / 256), 256>>>(Wh, 1);

    {
        dim3 grid(G4 / 64, MROWS / 128);   // (64, 256)
        gemm_mma_kernel<<<grid, 256, SMEM_DYN>>>();
    }

    lstm_mma_kernel<<<NCTA, 256, P2_SMEM>>>(b, out);
}

// round 16
// speedup vs baseline: 1.2535x; 1.1264x over previous
#include <cuda_runtime.h>
#include <cuda_bf16.h>
#include <math.h>
#include <cstdint>

// Problem constants
#define BATCH 64
#define TT    512
#define FF    1024
#define HH    1024
#define G4    4096
#define NCTA  256           // 64 N-groups x 4 K-splits, 2/SM co-resident
#define MROWS (BATCH * TT)

// ---------------- scratch (static device memory; no allocations) ------------
static __device__ float          g_xg[(size_t)MROWS * G4];
static __device__ __nv_bfloat16  g_xhi[(size_t)MROWS * FF];
static __device__ __nv_bfloat16  g_xlo[(size_t)MROWS * FF];
static __device__ __nv_bfloat16  g_wthi[(size_t)G4 * FF];     // WxT [n][k]
static __device__ __nv_bfloat16  g_wtlo[(size_t)G4 * FF];
static __device__ __nv_bfloat16  g_whthi[(size_t)G4 * HH];    // WhT [n][k]
static __device__ __nv_bfloat16  g_whtlo[(size_t)G4 * HH];
static __device__ __nv_bfloat16  g_hhi[4][BATCH * HH];        // h hi, mod-4 (skew-safe)
static __device__ __nv_bfloat16  g_hlo[4][BATCH * HH];        // h lo, mod-4
static __device__ float          g_zpart[2][NCTA * BATCH * 64]; // parity-2
static __device__ unsigned       g_flags[64];                 // zpart arrivals / group
static __device__ unsigned       g_qcount[4];                 // h-quarter pointwise arrivals
static __device__ unsigned       g_bar_count;                 // prologue barrier only
static __device__ volatile unsigned g_bar_gen;

// ======================= PTX helpers ========================================
__device__ __forceinline__ uint32_t smem_u32(const void* p) {
    uint32_t a;
    asm("{ .reg .u64 t; cvta.to.shared.u64 t, %1; cvt.u32.u64 %0, t; }"
        : "=r"(a) : "l"(p));
    return a;
}
__device__ __forceinline__ void ldsm_x4(uint32_t& r0, uint32_t& r1,
                                        uint32_t& r2, uint32_t& r3, uint32_t addr) {
    asm volatile("ldmatrix.sync.aligned.m8n8.x4.shared.b16 {%0,%1,%2,%3}, [%4];"
                 : "=r"(r0), "=r"(r1), "=r"(r2), "=r"(r3) : "r"(addr));
}
__device__ __forceinline__ void mma16816(float* d, const uint32_t* a, const uint32_t* b) {
    asm volatile(
        "mma.sync.aligned.m16n8k16.row.col.f32.bf16.bf16.f32 "
        "{%0,%1,%2,%3}, {%4,%5,%6,%7}, {%8,%9}, {%0,%1,%2,%3};"
        : "+f"(d[0]), "+f"(d[1]), "+f"(d[2]), "+f"(d[3])
        : "r"(a[0]), "r"(a[1]), "r"(a[2]), "r"(a[3]), "r"(b[0]), "r"(b[1]));
}
__device__ __forceinline__ void cpasync16(uint32_t dst, const void* src) {
    asm volatile("cp.async.cg.shared.global [%0], [%1], 16;" :: "r"(dst), "l"(src));
}
__device__ __forceinline__ void cpcommit() { asm volatile("cp.async.commit_group;" ::: "memory"); }
template<int N> __device__ __forceinline__ void cpwait() {
    asm volatile("cp.async.wait_group %0;" :: "n"(N) : "memory");
}
__device__ __forceinline__ uint32_t swA3(int row, int seg) {
    return (uint32_t)((row << 7) + ((seg ^ (row & 7)) << 4));
}
__device__ __forceinline__ uint32_t swB3(int n, int seg) {
    return (uint32_t)((n << 9) + ((seg ^ (n & 7)) << 4));
}

// ============================================================================
// Conversions
// ============================================================================
__global__ __launch_bounds__(256)
void convert_x_kernel(const float* __restrict__ x)
{
    size_t i = (size_t)blockIdx.x * blockDim.x + threadIdx.x;
    float4 v = ((const float4*)x)[i];
    float vv[4] = {v.x, v.y, v.z, v.w};
    __nv_bfloat16 hi[4], lo[4];
#pragma unroll
    for (int j = 0; j < 4; j++) {
        hi[j] = __float2bfloat16(vv[j]);
        lo[j] = __float2bfloat16(vv[j] - __bfloat162float(hi[j]));
    }
    __nv_bfloat162* xh = (__nv_bfloat162*)g_xhi;
    __nv_bfloat162* xl = (__nv_bfloat162*)g_xlo;
    xh[2 * i]     = __halves2bfloat162(hi[0], hi[1]);
    xh[2 * i + 1] = __halves2bfloat162(hi[2], hi[3]);
    xl[2 * i]     = __halves2bfloat162(lo[0], lo[1]);
    xl[2 * i + 1] = __halves2bfloat162(lo[2], lo[3]);
}

__global__ __launch_bounds__(256)
void convert_wt_kernel(const float* __restrict__ src, int which)
{
    __nv_bfloat16* dhi = which ? g_whthi : g_wthi;
    __nv_bfloat16* dlo = which ? g_whtlo : g_wtlo;
    size_t idx = (size_t)blockIdx.x * blockDim.x + threadIdx.x;
    int k = (int)(idx >> 12);
    int n = (int)(idx & 4095);
    float v = src[idx];
    __nv_bfloat16 hi = __float2bfloat16(v);
    __nv_bfloat16 lo = __float2bfloat16(v - __bfloat162float(hi));
    dhi[(size_t)n * FF + k] = hi;
    dlo[(size_t)n * FF + k] = lo;
}

// ============================================================================
// Phase 1: xg = x @ Wx. CTA 128x64, warp m32n32, KCHUNK=64, cp.async 2-stage.
// (validated R13)
// ============================================================================
#define P1_AHI 0
#define P1_ALO 16384
#define P1_BHI 32768
#define P1_BLO 40960
#define P1_BUF 49152
#define SMEM_DYN (2 * P1_BUF + 1024)
#define NCH1 16

__global__ __launch_bounds__(256, 2)
void gemm_mma_kernel()
{
    extern __shared__ char smem_raw[];
    char* smem = (char*)(((uintptr_t)smem_raw + 1023) & ~(uintptr_t)1023);
    const uint32_t sb = smem_u32(smem);

    const int tid = threadIdx.x;
    const int wid = tid >> 5;
    const int lane = tid & 31;
    const int wm = wid & 3;
    const int wn = wid >> 2;
    const int col0 = blockIdx.x * 64;
    const int row0 = blockIdx.y * 128;

    const int sr  = tid >> 3;
    const int ssg = tid & 7;

    float acc[2][4][4];
#pragma unroll
    for (int i = 0; i < 2; i++)
#pragma unroll
        for (int j = 0; j < 4; j++)
#pragma unroll
            for (int q = 0; q < 4; q++) acc[i][j][q] = 0.f;

    auto issue = [&](int c) {
        const uint32_t stg = (uint32_t)(c & 1) * P1_BUF;
        const int k0 = c * 64;
#pragma unroll
        for (int i = 0; i < 4; i++) {
            const int row = sr + 32 * i;
            const uint32_t so = swA3(row, ssg);
            const size_t src = (size_t)(row0 + row) * FF + k0 + ssg * 8;
            cpasync16(sb + stg + P1_AHI + so, g_xhi + src);
            cpasync16(sb + stg + P1_ALO + so, g_xlo + src);
        }
#pragma unroll
        for (int i = 0; i < 2; i++) {
            const int n = sr + 32 * i;
            const uint32_t so = swA3(n, ssg);
            const size_t src = (size_t)(col0 + n) * FF + k0 + ssg * 8;
            cpasync16(sb + stg + P1_BHI + so, g_wthi + src);
            cpasync16(sb + stg + P1_BLO + so, g_wtlo + src);
        }
        cpcommit();
    };

    issue(0);
    for (int c = 0; c < NCH1; c++) {
        if (c + 1 < NCH1) { issue(c + 1); cpwait<1>(); }
        else             { cpwait<0>(); }
        __syncthreads();

        const uint32_t stg = (uint32_t)(c & 1) * P1_BUF;
#pragma unroll
        for (int kk = 0; kk < 4; kk++) {
            const int lrow = lane & 15;
            const int lseg = 2 * kk + (lane >> 4);

            uint32_t ah[2][4], al[2][4];
#pragma unroll
            for (int i = 0; i < 2; i++) {
                const int r = 32 * wm + 16 * i + lrow;
                ldsm_x4(ah[i][0], ah[i][1], ah[i][2], ah[i][3],
                        sb + stg + P1_AHI + swA3(r, lseg));
                ldsm_x4(al[i][0], al[i][1], al[i][2], al[i][3],
                        sb + stg + P1_ALO + swA3(r, lseg));
            }
            uint32_t bh[4][2], bl[4][2];
#pragma unroll
            for (int jj = 0; jj < 2; jj++) {
                const int r = 32 * wn + 16 * jj + lrow;
                uint32_t r0, r1, r2, r3;
                ldsm_x4(r0, r1, r2, r3, sb + stg + P1_BHI + swA3(r, lseg));
                bh[2 * jj][0] = r0; bh[2 * jj][1] = r2;
                bh[2 * jj + 1][0] = r1; bh[2 * jj + 1][1] = r3;
                ldsm_x4(r0, r1, r2, r3, sb + stg + P1_BLO + swA3(r, lseg));
                bl[2 * jj][0] = r0; bl[2 * jj][1] = r2;
                bl[2 * jj + 1][0] = r1; bl[2 * jj + 1][1] = r3;
            }
#pragma unroll
            for (int i = 0; i < 2; i++)
#pragma unroll
                for (int j = 0; j < 4; j++) {
                    mma16816(acc[i][j], ah[i], bh[j]);
                    mma16816(acc[i][j], ah[i], bl[j]);
                    mma16816(acc[i][j], al[i], bh[j]);
                }
        }
        __syncthreads();
    }

    const int tq = lane >> 2;
    const int tr = lane & 3;
#pragma unroll
    for (int i = 0; i < 2; i++) {
        const int mbase = row0 + 32 * wm + 16 * i;
#pragma unroll
        for (int j = 0; j < 4; j++) {
            const int nbase = col0 + 32 * wn + 8 * j;
            float* p0 = &g_xg[(size_t)(mbase + tq) * G4 + nbase + 2 * tr];
            float* p1 = &g_xg[(size_t)(mbase + tq + 8) * G4 + nbase + 2 * tr];
            p0[0] = acc[i][j][0]; p0[1] = acc[i][j][1];
            p1[0] = acc[i][j][2]; p1[1] = acc[i][j][3];
        }
    }
}

// ============================================================================
// Phase 2: persistent K-split recurrence, dataflow sync (no global barrier).
// CTA (g,ks): waits quarter-counter[ks] (its h producers) instead of all CTAs.
// h mod-4 buffers (skew<=3 safe), zpart parity-2 (group flag bounds skew to 1).
// ============================================================================
#define P2_BHI   0
#define P2_BLO   32768
#define P2_A     65536
#define P2_ABUF  16384
#define P2_SMEM  (65536 + 32768 + 1024)

__device__ __forceinline__ float sigmoidf_(float v) { return 1.f / (1.f + expf(-v)); }

__global__ __launch_bounds__(256, 2)
void lstm_mma_kernel(const float* __restrict__ bias, float* __restrict__ out)
{
    extern __shared__ char smem_raw[];
    char* smem = (char*)(((uintptr_t)smem_raw + 1023) & ~(uintptr_t)1023);
    const uint32_t sb = smem_u32(smem);

    const int tid  = threadIdx.x;
    const int wid  = tid >> 5;
    const int lane = tid & 31;
    const int wm   = wid & 3;
    const int wn   = wid >> 2;
    const int g    = blockIdx.x >> 2;
    const int ks   = blockIdx.x & 3;
    const int kbase = ks * 256;
    const int myq  = g >> 4;              // quarter this CTA's h-columns live in

    const int pb = ks * 16 + (tid >> 4);
    const int hl = tid & 15;
    const int hcol = g * 16 + hl;
    float bb[4];
#pragma unroll
    for (int gt = 0; gt < 4; gt++) bb[gt] = bias[gt * 1024 + hcol];
    float cell = 0.f;

    // ---- resident B: 64 n x 256 k slice, hi/lo ----
#pragma unroll
    for (int i = 0; i < 8; i++) {
        int fi  = tid + i * 256;
        int n   = fi >> 5;
        int seg = fi & 31;
        int gn  = (n >> 4) * 1024 + g * 16 + (n & 15);
        uint32_t so = swB3(n, seg);
        const size_t src = (size_t)gn * HH + kbase + seg * 8;
        *(float4*)(smem + P2_BHI + so) = *(const float4*)(g_whthi + src);
        *(float4*)(smem + P2_BLO + so) = *(const float4*)(g_whtlo + src);
    }

    // ---- capture counter bases (tid0 registers), then one prologue barrier ----
    unsigned fbase = 0, qbase = 0;
    if (tid == 0) {
        fbase = g_flags[g];
        qbase = g_qcount[ks];
    }
    __threadfence();
    __syncthreads();
    if (tid == 0) {
        unsigned gen = g_bar_gen;
        if (atomicAdd(&g_bar_count, 1) == NCTA - 1) {
            g_bar_count = 0;
            __threadfence();
            g_bar_gen = gen + 1;
        } else {
            while (g_bar_gen == gen) { __nanosleep(32); }
        }
    }
    __syncthreads();

    const int ar  = tid >> 3;
    const int asg = tid & 7;

    for (int t = 0; t < TT; t++) {
        float xv[4];
#pragma unroll
        for (int gt = 0; gt < 4; gt++)
            xv[gt] = g_xg[((size_t)pb * TT + t) * G4 + gt * 1024 + hcol];

        float* zpart_self = g_zpart[t & 1] + (size_t)(g * 4 + ks) * BATCH * 64;

        if (t > 0) {
            // ---- wait only on h-quarter producers (64 CTAs), not all 256 ----
            if (tid == 0) {
                const unsigned tgt = qbase + 64u * (unsigned)t;
                while ((int)(*(volatile unsigned*)&g_qcount[ks] - tgt) < 0)
                    __nanosleep(32);
            }
            __syncthreads();

            const __nv_bfloat16* hh  = g_hhi[(t - 1) & 3];
            const __nv_bfloat16* hl_ = g_hlo[(t - 1) & 3];

            float acc[4][4];
#pragma unroll
            for (int j = 0; j < 4; j++)
#pragma unroll
                for (int q = 0; q < 4; q++) acc[j][q] = 0.f;

            auto issueA = [&](int kc) {
                const uint32_t abase = P2_A + (uint32_t)(kc & 1) * P2_ABUF;
                const int kn = kbase + kc * 64;
#pragma unroll
                for (int i = 0; i < 2; i++) {
                    const int row = ar + 32 * i;
                    const uint32_t so = swA3(row, asg);
                    const size_t off = (size_t)row * HH + kn + asg * 8;
                    cpasync16(sb + abase + so,        hh  + off);
                    cpasync16(sb + abase + 8192 + so, hl_ + off);
                }
                cpcommit();
            };

            issueA(0);
            for (int kc = 0; kc < 4; kc++) {
                if (kc + 1 < 4) { issueA(kc + 1); cpwait<1>(); }
                else            { cpwait<0>(); }
                __syncthreads();

                const uint32_t abase = P2_A + (uint32_t)(kc & 1) * P2_ABUF;
#pragma unroll
                for (int kk = 0; kk < 4; kk++) {
                    const int lrow = lane & 15;
                    const int hs   = lane >> 4;
                    const int aseg2 = 2 * kk + hs;
                    const int bseg2 = 2 * (kc * 4 + kk) + hs;

                    uint32_t ah[4], al[4];
                    ldsm_x4(ah[0], ah[1], ah[2], ah[3],
                            sb + abase + swA3(wm * 16 + lrow, aseg2));
                    ldsm_x4(al[0], al[1], al[2], al[3],
                            sb + abase + 8192 + swA3(wm * 16 + lrow, aseg2));

                    uint32_t bh[4][2], bl[4][2];
#pragma unroll
                    for (int jj = 0; jj < 2; jj++) {
                        const int r = wn * 32 + 16 * jj + lrow;
                        uint32_t r0, r1, r2, r3;
                        ldsm_x4(r0, r1, r2, r3, sb + P2_BHI + swB3(r, bseg2));
                        bh[2 * jj][0] = r0; bh[2 * jj][1] = r2;
                        bh[2 * jj + 1][0] = r1; bh[2 * jj + 1][1] = r3;
                        ldsm_x4(r0, r1, r2, r3, sb + P2_BLO + swB3(r, bseg2));
                        bl[2 * jj][0] = r0; bl[2 * jj][1] = r2;
                        bl[2 * jj + 1][0] = r1; bl[2 * jj + 1][1] = r3;
                    }
#pragma unroll
                    for (int j = 0; j < 4; j++) {
                        mma16816(acc[j], ah, bh[j]);
                        mma16816(acc[j], ah, bl[j]);
                        mma16816(acc[j], al, bh[j]);
                    }
                }
                __syncthreads();
            }

            // write partials (parity buffer)
            {
                const int r = wm * 16 + (lane >> 2);
#pragma unroll
                for (int j = 0; j < 4; j++) {
                    const int n = wn * 32 + 8 * j + (lane & 3) * 2;
                    zpart_self[r * 64 + n]           = acc[j][0];
                    zpart_self[r * 64 + n + 1]       = acc[j][1];
                    zpart_self[(r + 8) * 64 + n]     = acc[j][2];
                    zpart_self[(r + 8) * 64 + n + 1] = acc[j][3];
                }
            }

            // per-group zpart flag sync (release; consumers use __ldcv)
            __threadfence();
            __syncthreads();
            if (tid == 0) {
                atomicAdd(&g_flags[g], 1u);
                const unsigned tgt = fbase + 4u * (unsigned)t;
                while ((int)(*(volatile unsigned*)&g_flags[g] - tgt) < 0)
                    __nanosleep(32);
            }
            __syncthreads();
        }

        // ---- pointwise (zpart via __ldcv) ----
        {
            const float* zp = g_zpart[t & 1];
            float z[4];
#pragma unroll
            for (int gt = 0; gt < 4; gt++) {
                float s = xv[gt] + bb[gt];
                if (t > 0) {
                    const int n = gt * 16 + hl;
#pragma unroll
                    for (int k2 = 0; k2 < 4; k2++)
                        s += __ldcv(&zp[((size_t)(g * 4 + k2) * BATCH + pb) * 64 + n]);
                }
                z[gt] = s;
            }
            float cn = sigmoidf_(z[1]) * cell + sigmoidf_(z[0]) * tanhf(z[2]);
            float hn = sigmoidf_(z[3]) * tanhf(cn);
            cell = cn;

            out[((size_t)pb * TT + t) * HH + hcol] = hn;
            __nv_bfloat16 hi = __float2bfloat16(hn);
            __nv_bfloat16 lo = __float2bfloat16(hn - __bfloat162float(hi));
            g_hhi[t & 3][pb * HH + hcol] = hi;
            g_hlo[t & 3][pb * HH + hcol] = lo;
        }

        // ---- announce h-quarter completion (release), then continue ----
        __threadfence();
        __syncthreads();
        if (tid == 0) atomicAdd(&g_qcount[myq], 1u);
    }
}

// ============================================================================
// Launch: 5 graph nodes.
// ============================================================================
extern "C" void kernel_launch(void* const* d_in, const int* in_sizes, int n_in,
                              void* d_out, int out_size)
{
    const float* x  = (const float*)d_in[0];
    const float* Wx = (const float*)d_in[1];
    const float* Wh = (const float*)d_in[2];
    const float* b  = (const float*)d_in[3];
    float* out = (float*)d_out;

    cudaFuncSetAttribute(gemm_mma_kernel,
                         cudaFuncAttributeMaxDynamicSharedMemorySize, SMEM_DYN);
    cudaFuncSetAttribute(lstm_mma_kernel,
                         cudaFuncAttributeMaxDynamicSharedMemorySize, P2_SMEM);

    convert_x_kernel<<<(int)(((size_t)MROWS * FF / 4) / 256), 256>>>(x);
    convert_wt_kernel<<<(int)(((size_t)FF * G4) / 256), 256>>>(Wx, 0);
    convert_wt_kernel<<<(int)(((size_t)FF * G4) / 256), 256>>>(Wh, 1);

    {
        dim3 grid(G4 / 64, MROWS / 128);   // (64, 256)
        gemm_mma_kernel<<<grid, 256, SMEM_DYN>>>();
    }

    lstm_mma_kernel<<<NCTA, 256, P2_SMEM>>>(b, out);
}